// round 1
// baseline (speedup 1.0000x reference)
#include <cuda_runtime.h>
#include <cuda_bf16.h>
#include <mma.h>
#include <math.h>

using namespace nvcuda;

#define D_      1024
#define S_      8192
#define B_      4
#define NROWS   (B_ * S_)      // 32768
#define E3      (3 * D_)       // 3072
#define GROUPS  256            // row-groups per batch
#define GSIZE   32             // rows per group (GROUPS*GSIZE = S_)

// ---------------- scratch (static __device__: allocation-free) ----------------
__device__ __nv_bfloat16 g_Xn  [(size_t)NROWS * D_];   // 64 MiB
__device__ __nv_bfloat16 g_Win [(size_t)E3 * D_];      // 6 MiB
__device__ __nv_bfloat16 g_Wout[(size_t)D_ * D_];      // 2 MiB
__device__ float         g_QKV [(size_t)NROWS * E3];   // 384 MiB (Q slot reused for Qhat)
__device__ float         g_Apart[B_ * GROUPS * D_];    // 4 MiB
__device__ float         g_A   [B_ * D_];
__device__ __nv_bfloat16 g_Y   [(size_t)NROWS * D_];   // 64 MiB

// ---------------- fp32 -> bf16 weight conversion ----------------
__global__ void k_convert(const float* __restrict__ src, int which, int n)
{
    int i = (blockIdx.x * blockDim.x + threadIdx.x) * 4;
    if (i >= n) return;
    __nv_bfloat16* dst = which ? g_Wout : g_Win;
    float4 v = *(const float4*)(src + i);
    __nv_bfloat162 p0 = __floats2bfloat162_rn(v.x, v.y);
    __nv_bfloat162 p1 = __floats2bfloat162_rn(v.z, v.w);
    *(__nv_bfloat162*)(dst + i)     = p0;
    *(__nv_bfloat162*)(dst + i + 2) = p1;
}

// ---------------- LayerNorm (one block per row) ----------------
__global__ void __launch_bounds__(256) k_layernorm(
    const float* __restrict__ X, const float* __restrict__ lg, const float* __restrict__ lb)
{
    int row = blockIdx.x;
    int t   = threadIdx.x;
    const float* xp = X + (size_t)row * D_ + 4 * t;
    float4 x = *(const float4*)xp;

    float s  = x.x + x.y + x.z + x.w;
    float sq = x.x * x.x + x.y * x.y + x.z * x.z + x.w * x.w;

    __shared__ float2 red[9];
    float2 v = make_float2(s, sq);
    #pragma unroll
    for (int o = 16; o; o >>= 1) {
        v.x += __shfl_xor_sync(0xffffffffu, v.x, o);
        v.y += __shfl_xor_sync(0xffffffffu, v.y, o);
    }
    if ((t & 31) == 0) red[t >> 5] = v;
    __syncthreads();
    if (t < 32) {
        float2 w = (t < 8) ? red[t] : make_float2(0.f, 0.f);
        #pragma unroll
        for (int o = 4; o; o >>= 1) {
            w.x += __shfl_xor_sync(0xffffffffu, w.x, o);
            w.y += __shfl_xor_sync(0xffffffffu, w.y, o);
        }
        if (t == 0) red[8] = w;
    }
    __syncthreads();
    float2 tot = red[8];

    float mu  = tot.x * (1.f / D_);
    float var = tot.y * (1.f / D_) - mu * mu;
    float rs  = rsqrtf(var + 1e-5f);

    float4 g4 = *(const float4*)(lg + 4 * t);
    float4 b4 = *(const float4*)(lb + 4 * t);
    float y0 = (x.x - mu) * rs * g4.x + b4.x;
    float y1 = (x.y - mu) * rs * g4.y + b4.y;
    float y2 = (x.z - mu) * rs * g4.z + b4.z;
    float y3 = (x.w - mu) * rs * g4.w + b4.w;

    __nv_bfloat16* op = g_Xn + (size_t)row * D_ + 4 * t;
    *(__nv_bfloat162*)(op)     = __floats2bfloat162_rn(y0, y1);
    *(__nv_bfloat162*)(op + 2) = __floats2bfloat162_rn(y2, y3);
}

// ---------------- bf16 GEMM: C[m,n] = sum_k A[m,k]*W[n,k] (+X)  ----------------
// mode 0: A=g_Xn, W=g_Win, C=g_QKV, N=3072
// mode 1: A=g_Y,  W=g_Wout, C=Cout, N=1024, epilogue += addX
__global__ void __launch_bounds__(256) k_gemm(
    const float* __restrict__ addX, float* __restrict__ Cout, int mode, int N)
{
    const int K = 1024;
    __shared__ __align__(16) __nv_bfloat16 As[128 * 40];
    __shared__ __align__(16) __nv_bfloat16 Bs[128 * 40];
    __shared__ __align__(16) float esc[8][256];

    int tid = threadIdx.x;
    int w   = tid >> 5;
    int lane = tid & 31;
    int wm = w & 1;          // 0..1  -> 64-row slice
    int wn = w >> 1;         // 0..3  -> 32-col slice
    int m0 = blockIdx.y * 128;
    int n0 = blockIdx.x * 128;

    const __nv_bfloat16* Ag = (mode ? g_Y : g_Xn) + (size_t)m0 * K;
    const __nv_bfloat16* Bg = (mode ? g_Wout : g_Win) + (size_t)n0 * K;
    float* C = mode ? Cout : g_QKV;

    wmma::fragment<wmma::accumulator, 16, 16, 16, float> acc[4][2];
    #pragma unroll
    for (int i = 0; i < 4; i++)
        #pragma unroll
        for (int j = 0; j < 2; j++)
            wmma::fill_fragment(acc[i][j], 0.f);

    int r0  = tid >> 2;          // 0..63
    int k8  = (tid & 3) * 8;
    int r1  = r0 + 64;

    for (int kt = 0; kt < K; kt += 32) {
        *(uint4*)&As[r0 * 40 + k8] = *(const uint4*)(Ag + (size_t)r0 * K + kt + k8);
        *(uint4*)&As[r1 * 40 + k8] = *(const uint4*)(Ag + (size_t)r1 * K + kt + k8);
        *(uint4*)&Bs[r0 * 40 + k8] = *(const uint4*)(Bg + (size_t)r0 * K + kt + k8);
        *(uint4*)&Bs[r1 * 40 + k8] = *(const uint4*)(Bg + (size_t)r1 * K + kt + k8);
        __syncthreads();

        #pragma unroll
        for (int ks = 0; ks < 32; ks += 16) {
            wmma::fragment<wmma::matrix_a, 16, 16, 16, __nv_bfloat16, wmma::row_major> af[4];
            wmma::fragment<wmma::matrix_b, 16, 16, 16, __nv_bfloat16, wmma::col_major> bf[2];
            #pragma unroll
            for (int i = 0; i < 4; i++)
                wmma::load_matrix_sync(af[i], &As[(wm * 64 + i * 16) * 40 + ks], 40);
            #pragma unroll
            for (int j = 0; j < 2; j++)
                wmma::load_matrix_sync(bf[j], &Bs[(wn * 32 + j * 16) * 40 + ks], 40);
            #pragma unroll
            for (int i = 0; i < 4; i++)
                #pragma unroll
                for (int j = 0; j < 2; j++)
                    wmma::mma_sync(acc[i][j], af[i], bf[j], acc[i][j]);
        }
        __syncthreads();
    }

    if (!addX) {
        #pragma unroll
        for (int i = 0; i < 4; i++)
            #pragma unroll
            for (int j = 0; j < 2; j++) {
                float* dst = C + (size_t)(m0 + wm * 64 + i * 16) * N + (n0 + wn * 32 + j * 16);
                wmma::store_matrix_sync(dst, acc[i][j], N, wmma::mem_row_major);
            }
    } else {
        int rr = lane >> 1;
        int cc = (lane & 1) * 8;
        #pragma unroll
        for (int i = 0; i < 4; i++)
            #pragma unroll
            for (int j = 0; j < 2; j++) {
                wmma::store_matrix_sync(esc[w], acc[i][j], 16, wmma::mem_row_major);
                __syncwarp();
                size_t gi = (size_t)(m0 + wm * 64 + i * 16 + rr) * N + (n0 + wn * 32 + j * 16 + cc);
                float4 a0 = *(float4*)&esc[w][rr * 16 + cc];
                float4 a1 = *(float4*)&esc[w][rr * 16 + cc + 4];
                float4 x0 = *(const float4*)(addX + gi);
                float4 x1 = *(const float4*)(addX + gi + 4);
                a0.x += x0.x; a0.y += x0.y; a0.z += x0.z; a0.w += x0.w;
                a1.x += x1.x; a1.y += x1.y; a1.z += x1.z; a1.w += x1.w;
                *(float4*)(C + gi)     = a0;
                *(float4*)(C + gi + 4) = a1;
                __syncwarp();
            }
    }
}

// ---------------- rotary + l2norms + A partial reduction ----------------
// One block per (batch, 32-row group). Writes Qhat in place of Q; accumulates
// per-group A partials (deterministic, no atomics).
__global__ void __launch_bounds__(256) k_rowproc()
{
    int bg = blockIdx.x;
    int b  = bg >> 8;
    int g  = bg & 255;
    int t  = threadIdx.x;
    int d0 = 4 * t;

    float invf0 = 0.f, invf1 = 0.f;
    bool rot = (d0 < 512);
    if (rot) {
        int i0 = 2 * t;     // rotary pair index, exponent i/256
        invf0 = (float)(1.0 / pow(10000.0, (double)i0 * (1.0 / 256.0)));
        invf1 = (float)(1.0 / pow(10000.0, (double)(i0 + 1) * (1.0 / 256.0)));
    }

    float accA0 = 0.f, accA1 = 0.f, accA2 = 0.f, accA3 = 0.f;
    __shared__ float2 red[2][9];

    for (int r = 0; r < GSIZE; r++) {
        int s = g * GSIZE + r;
        size_t base = ((size_t)b * S_ + s) * E3;
        float4 q = *(float4*)&g_QKV[base + d0];
        float4 k = *(float4*)&g_QKV[base + 1024 + d0];
        float4 v = *(float4*)&g_QKV[base + 2048 + d0];

        if (rot) {
            float sn0, cs0, sn1, cs1;
            sincosf((float)s * invf0, &sn0, &cs0);
            sincosf((float)s * invf1, &sn1, &cs1);
            float a, bb;
            a = q.x * cs0 - q.y * sn0; bb = q.y * cs0 + q.x * sn0; q.x = a; q.y = bb;
            a = q.z * cs1 - q.w * sn1; bb = q.w * cs1 + q.z * sn1; q.z = a; q.w = bb;
            a = k.x * cs0 - k.y * sn0; bb = k.y * cs0 + k.x * sn0; k.x = a; k.y = bb;
            a = k.z * cs1 - k.w * sn1; bb = k.w * cs1 + k.z * sn1; k.z = a; k.w = bb;
        }

        float sk = k.x * k.x + k.y * k.y + k.z * k.z + k.w * k.w;
        float sq = q.x * q.x + q.y * q.y + q.z * q.z + q.w * q.w;
        float2 val = make_float2(sk, sq);
        #pragma unroll
        for (int o = 16; o; o >>= 1) {
            val.x += __shfl_xor_sync(0xffffffffu, val.x, o);
            val.y += __shfl_xor_sync(0xffffffffu, val.y, o);
        }
        int par = r & 1;
        if ((t & 31) == 0) red[par][t >> 5] = val;
        __syncthreads();
        if (t < 32) {
            float2 w2 = (t < 8) ? red[par][t] : make_float2(0.f, 0.f);
            #pragma unroll
            for (int o = 4; o; o >>= 1) {
                w2.x += __shfl_xor_sync(0xffffffffu, w2.x, o);
                w2.y += __shfl_xor_sync(0xffffffffu, w2.y, o);
            }
            if (t == 0) red[par][8] = w2;
        }
        __syncthreads();
        float2 tot = red[par][8];
        float kinv = rsqrtf(tot.x + 1e-6f);
        float qinv = rsqrtf(tot.y + 1e-6f);

        accA0 += k.x * kinv * v.x;
        accA1 += k.y * kinv * v.y;
        accA2 += k.z * kinv * v.z;
        accA3 += k.w * kinv * v.w;

        float4 qh = make_float4(q.x * qinv, q.y * qinv, q.z * qinv, q.w * qinv);
        *(float4*)&g_QKV[base + d0] = qh;   // Qhat in place
    }

    size_t ap = ((size_t)(b * GROUPS + g)) * D_ + d0;
    *(float4*)&g_Apart[ap] = make_float4(accA0, accA1, accA2, accA3);
}

// ---------------- reduce A partials ----------------
__global__ void k_reduceA()
{
    int idx = blockIdx.x * blockDim.x + threadIdx.x;   // 0..4095
    int b  = idx >> 10;
    int dd = idx & 1023;
    const float* p = g_Apart + (size_t)b * GROUPS * D_ + dd;
    float s = 0.f;
    #pragma unroll 8
    for (int g = 0; g < GROUPS; g++) s += p[(size_t)g * D_];
    g_A[idx] = s;
}

// ---------------- Y = A (*) Qhat  -> bf16 ----------------
__global__ void __launch_bounds__(256) k_scaleY()
{
    size_t row = blockIdx.x;
    int t  = threadIdx.x;
    int d0 = 4 * t;
    int b  = (int)(row >> 13);
    float4 q = *(float4*)&g_QKV[row * E3 + d0];
    float4 a = *(const float4*)&g_A[b * D_ + d0];
    __nv_bfloat16* op = g_Y + row * D_ + d0;
    *(__nv_bfloat162*)(op)     = __floats2bfloat162_rn(q.x * a.x, q.y * a.y);
    *(__nv_bfloat162*)(op + 2) = __floats2bfloat162_rn(q.z * a.z, q.w * a.w);
}

// ---------------- launch ----------------
extern "C" void kernel_launch(void* const* d_in, const int* in_sizes, int n_in,
                              void* d_out, int out_size)
{
    const float* X    = (const float*)d_in[0];
    const float* Win  = (const float*)d_in[1];
    const float* Wout = (const float*)d_in[2];
    const float* lg   = (const float*)d_in[3];
    const float* lb   = (const float*)d_in[4];
    float* out = (float*)d_out;

    k_convert<<<(E3 * D_) / 4 / 256, 256>>>(Win, 0, E3 * D_);
    k_convert<<<(D_ * D_) / 4 / 256, 256>>>(Wout, 1, D_ * D_);
    k_layernorm<<<NROWS, 256>>>(X, lg, lb);
    k_gemm<<<dim3(E3 / 128, NROWS / 128), 256>>>(nullptr, out, 0, E3);
    k_rowproc<<<B_ * GROUPS, 256>>>();
    k_reduceA<<<16, 256>>>();
    k_scaleY<<<NROWS, 256>>>();
    k_gemm<<<dim3(D_ / 128, NROWS / 128), 256>>>(X, out, 1, D_);
}

// round 4
// speedup vs baseline: 1.0095x; 1.0095x over previous
#include <cuda_runtime.h>
#include <cuda_bf16.h>
#include <math.h>
#include <stdint.h>

#define D_      1024
#define S_      8192
#define B_      4
#define NROWS   (B_ * S_)      // 32768
#define E3      (3 * D_)       // 3072
#define GROUPS  256
#define GSIZE   32

// ---------------- scratch (static __device__: allocation-free) ----------------
__device__ __nv_bfloat16 g_Xn  [(size_t)NROWS * D_];   // 64 MiB
__device__ __nv_bfloat16 g_Win [(size_t)E3 * D_];      // 6 MiB
__device__ __nv_bfloat16 g_Wout[(size_t)D_ * D_];      // 2 MiB
__device__ float         g_QKV [(size_t)NROWS * E3];   // 384 MiB (Q slot reused for Qhat)
__device__ float         g_Apart[B_ * GROUPS * D_];
__device__ float         g_A   [B_ * D_];
__device__ __nv_bfloat16 g_Y   [(size_t)NROWS * D_];   // 64 MiB

__device__ __forceinline__ uint32_t smem_u32(const void* p) {
    uint32_t a;
    asm("{ .reg .u64 t; cvta.to.shared.u64 t, %1; cvt.u32.u64 %0, t; }" : "=r"(a) : "l"(p));
    return a;
}

// ---------------- fp32 -> bf16 weight conversion ----------------
__global__ void k_convert(const float* __restrict__ src, int which, int n)
{
    int i = (blockIdx.x * blockDim.x + threadIdx.x) * 4;
    if (i >= n) return;
    __nv_bfloat16* dst = which ? g_Wout : g_Win;
    float4 v = *(const float4*)(src + i);
    *(__nv_bfloat162*)(dst + i)     = __floats2bfloat162_rn(v.x, v.y);
    *(__nv_bfloat162*)(dst + i + 2) = __floats2bfloat162_rn(v.z, v.w);
}

// ---------------- LayerNorm (one block per row) ----------------
__global__ void __launch_bounds__(256) k_layernorm(
    const float* __restrict__ X, const float* __restrict__ lg, const float* __restrict__ lb)
{
    int row = blockIdx.x;
    int t   = threadIdx.x;
    const float* xp = X + (size_t)row * D_ + 4 * t;
    float4 x = *(const float4*)xp;

    float s  = x.x + x.y + x.z + x.w;
    float sq = x.x * x.x + x.y * x.y + x.z * x.z + x.w * x.w;

    __shared__ float2 red[9];
    float2 v = make_float2(s, sq);
    #pragma unroll
    for (int o = 16; o; o >>= 1) {
        v.x += __shfl_xor_sync(0xffffffffu, v.x, o);
        v.y += __shfl_xor_sync(0xffffffffu, v.y, o);
    }
    if ((t & 31) == 0) red[t >> 5] = v;
    __syncthreads();
    if (t < 32) {
        float2 w = (t < 8) ? red[t] : make_float2(0.f, 0.f);
        #pragma unroll
        for (int o = 4; o; o >>= 1) {
            w.x += __shfl_xor_sync(0xffffffffu, w.x, o);
            w.y += __shfl_xor_sync(0xffffffffu, w.y, o);
        }
        if (t == 0) red[8] = w;
    }
    __syncthreads();
    float2 tot = red[8];

    float mu  = tot.x * (1.f / D_);
    float var = tot.y * (1.f / D_) - mu * mu;
    float rs  = rsqrtf(var + 1e-5f);

    float4 g4 = *(const float4*)(lg + 4 * t);
    float4 b4 = *(const float4*)(lb + 4 * t);
    float y0 = (x.x - mu) * rs * g4.x + b4.x;
    float y1 = (x.y - mu) * rs * g4.y + b4.y;
    float y2 = (x.z - mu) * rs * g4.z + b4.z;
    float y3 = (x.w - mu) * rs * g4.w + b4.w;

    __nv_bfloat16* op = g_Xn + (size_t)row * D_ + 4 * t;
    *(__nv_bfloat162*)(op)     = __floats2bfloat162_rn(y0, y1);
    *(__nv_bfloat162*)(op + 2) = __floats2bfloat162_rn(y2, y3);
}

// ---------------- mma.sync bf16 GEMM: C[m,n] = sum_k A[m,k]*W[n,k] (+X) ----------------
// 128x128 tile, 8 warps (4m x 2n), warp tile 32x64, KC=64, 3-stage cp.async.
#define KC 64
#define NCHUNK 16
#define STAGE_BYTES 32768          // A 16KB + B 16KB
#define GEMM_SMEM (3 * STAGE_BYTES)

__global__ void __launch_bounds__(256, 2) k_gemm(
    const float* __restrict__ addX, float* __restrict__ Cout, int mode, int N)
{
    extern __shared__ char smem[];
    const int K = 1024;
    const int tid  = threadIdx.x;
    const int w    = tid >> 5;
    const int lane = tid & 31;
    const int wm   = w & 3;          // 0..3 -> 32-row slice
    const int wn   = w >> 2;         // 0..1 -> 64-col slice
    const int m0 = blockIdx.y * 128;
    const int n0 = blockIdx.x * 128;

    const __nv_bfloat16* Ag = mode ? g_Y    : g_Xn;
    const __nv_bfloat16* Bg = mode ? g_Wout : g_Win;
    float* C = mode ? Cout : g_QKV;

    const uint32_t sbase = smem_u32(smem);

    auto issue = [&](int kt) {
        const uint32_t st = sbase + (kt % 3) * STAGE_BYTES;
        #pragma unroll
        for (int i = 0; i < 8; i++) {
            int vec = i * 256 + tid;          // 0..2047 ; A: 0-1023, B: 1024-2047
            int isB = vec >> 10;
            int v   = vec & 1023;
            int row = v >> 3;
            int c   = v & 7;
            const __nv_bfloat16* src =
                (isB ? Bg + (size_t)(n0 + row) * K : Ag + (size_t)(m0 + row) * K)
                + kt * KC + c * 8;
            uint32_t dst = st + isB * 16384 + row * 128 + (((c ^ (row & 7)) << 4));
            asm volatile("cp.async.cg.shared.global [%0], [%1], 16;" :: "r"(dst), "l"(src));
        }
        asm volatile("cp.async.commit_group;" ::: "memory");
    };

    float acc[2][8][4];
    #pragma unroll
    for (int mi = 0; mi < 2; mi++)
        #pragma unroll
        for (int ni = 0; ni < 8; ni++)
            #pragma unroll
            for (int e = 0; e < 4; e++) acc[mi][ni][e] = 0.f;

    issue(0); issue(1); issue(2);

    const int lr = lane & 15;
    const int lc = lane >> 4;

    for (int kt = 0; kt < NCHUNK; kt++) {
        asm volatile("cp.async.wait_group 2;" ::: "memory");
        __syncthreads();

        const uint32_t sA = sbase + (kt % 3) * STAGE_BYTES;
        const uint32_t sB = sA + 16384;

        #pragma unroll
        for (int ks = 0; ks < 4; ks++) {
            uint32_t a[2][4], b[8][2];
            #pragma unroll
            for (int mi = 0; mi < 2; mi++) {
                int r = wm * 32 + mi * 16 + lr;
                int c = ks * 2 + lc;
                uint32_t addr = sA + r * 128 + ((c ^ (r & 7)) << 4);
                asm volatile("ldmatrix.sync.aligned.m8n8.x4.shared.b16 {%0,%1,%2,%3}, [%4];"
                    : "=r"(a[mi][0]), "=r"(a[mi][1]), "=r"(a[mi][2]), "=r"(a[mi][3]) : "r"(addr));
            }
            #pragma unroll
            for (int nb = 0; nb < 4; nb++) {
                int r = wn * 64 + nb * 16 + lr;
                int c = ks * 2 + lc;
                uint32_t addr = sB + r * 128 + ((c ^ (r & 7)) << 4);
                uint32_t t0, t1, t2, t3;
                asm volatile("ldmatrix.sync.aligned.m8n8.x4.shared.b16 {%0,%1,%2,%3}, [%4];"
                    : "=r"(t0), "=r"(t1), "=r"(t2), "=r"(t3) : "r"(addr));
                b[nb * 2][0] = t0; b[nb * 2][1] = t2;
                b[nb * 2 + 1][0] = t1; b[nb * 2 + 1][1] = t3;
            }
            #pragma unroll
            for (int mi = 0; mi < 2; mi++)
                #pragma unroll
                for (int ni = 0; ni < 8; ni++) {
                    asm volatile(
                        "mma.sync.aligned.m16n8k16.row.col.f32.bf16.bf16.f32 "
                        "{%0,%1,%2,%3}, {%4,%5,%6,%7}, {%8,%9}, {%0,%1,%2,%3};"
                        : "+f"(acc[mi][ni][0]), "+f"(acc[mi][ni][1]),
                          "+f"(acc[mi][ni][2]), "+f"(acc[mi][ni][3])
                        : "r"(a[mi][0]), "r"(a[mi][1]), "r"(a[mi][2]), "r"(a[mi][3]),
                          "r"(b[ni][0]), "r"(b[ni][1]));
                }
        }
        __syncthreads();

        if (kt + 3 < NCHUNK) issue(kt + 3);
        else asm volatile("cp.async.commit_group;" ::: "memory");
    }

    // Epilogue: direct register -> gmem (float2), +X residual for mode 1.
    const int rbase = m0 + wm * 32 + (lane >> 2);
    const int cbase = n0 + wn * 64 + (lane & 3) * 2;
    #pragma unroll
    for (int mi = 0; mi < 2; mi++)
        #pragma unroll
        for (int ni = 0; ni < 8; ni++) {
            int rr = rbase + mi * 16;
            int cc = cbase + ni * 8;
            size_t i0 = (size_t)rr * N + cc;
            size_t i1 = (size_t)(rr + 8) * N + cc;
            float2 v0 = make_float2(acc[mi][ni][0], acc[mi][ni][1]);
            float2 v1 = make_float2(acc[mi][ni][2], acc[mi][ni][3]);
            if (addX) {
                float2 x0 = *(const float2*)(addX + i0);
                float2 x1 = *(const float2*)(addX + i1);
                v0.x += x0.x; v0.y += x0.y;
                v1.x += x1.x; v1.y += x1.y;
            }
            *(float2*)(C + i0) = v0;
            *(float2*)(C + i1) = v1;
        }
}

// ---------------- rotary + l2norms + A partial reduction ----------------
__global__ void __launch_bounds__(256) k_rowproc()
{
    int bg = blockIdx.x;
    int b  = bg >> 8;
    int g  = bg & 255;
    int t  = threadIdx.x;
    int d0 = 4 * t;

    float invf0 = 0.f, invf1 = 0.f;
    bool rot = (d0 < 512);
    if (rot) {
        int i0 = 2 * t;
        invf0 = (float)(1.0 / pow(10000.0, (double)i0 * (1.0 / 256.0)));
        invf1 = (float)(1.0 / pow(10000.0, (double)(i0 + 1) * (1.0 / 256.0)));
    }

    float accA0 = 0.f, accA1 = 0.f, accA2 = 0.f, accA3 = 0.f;
    __shared__ float2 red[2][9];

    for (int r = 0; r < GSIZE; r++) {
        int s = g * GSIZE + r;
        size_t base = ((size_t)b * S_ + s) * E3;
        float4 q = *(float4*)&g_QKV[base + d0];
        float4 k = *(float4*)&g_QKV[base + 1024 + d0];
        float4 v = *(float4*)&g_QKV[base + 2048 + d0];

        if (rot) {
            float sn0, cs0, sn1, cs1;
            sincosf((float)s * invf0, &sn0, &cs0);
            sincosf((float)s * invf1, &sn1, &cs1);
            float a, bb;
            a = q.x * cs0 - q.y * sn0; bb = q.y * cs0 + q.x * sn0; q.x = a; q.y = bb;
            a = q.z * cs1 - q.w * sn1; bb = q.w * cs1 + q.z * sn1; q.z = a; q.w = bb;
            a = k.x * cs0 - k.y * sn0; bb = k.y * cs0 + k.x * sn0; k.x = a; k.y = bb;
            a = k.z * cs1 - k.w * sn1; bb = k.w * cs1 + k.z * sn1; k.z = a; k.w = bb;
        }

        float sk = k.x * k.x + k.y * k.y + k.z * k.z + k.w * k.w;
        float sq = q.x * q.x + q.y * q.y + q.z * q.z + q.w * q.w;
        float2 val = make_float2(sk, sq);
        #pragma unroll
        for (int o = 16; o; o >>= 1) {
            val.x += __shfl_xor_sync(0xffffffffu, val.x, o);
            val.y += __shfl_xor_sync(0xffffffffu, val.y, o);
        }
        int par = r & 1;
        if ((t & 31) == 0) red[par][t >> 5] = val;
        __syncthreads();
        if (t < 32) {
            float2 w2 = (t < 8) ? red[par][t] : make_float2(0.f, 0.f);
            #pragma unroll
            for (int o = 4; o; o >>= 1) {
                w2.x += __shfl_xor_sync(0xffffffffu, w2.x, o);
                w2.y += __shfl_xor_sync(0xffffffffu, w2.y, o);
            }
            if (t == 0) red[par][8] = w2;
        }
        __syncthreads();
        float2 tot = red[par][8];
        float kinv = rsqrtf(tot.x + 1e-6f);
        float qinv = rsqrtf(tot.y + 1e-6f);

        accA0 += k.x * kinv * v.x;
        accA1 += k.y * kinv * v.y;
        accA2 += k.z * kinv * v.z;
        accA3 += k.w * kinv * v.w;

        float4 qh = make_float4(q.x * qinv, q.y * qinv, q.z * qinv, q.w * qinv);
        *(float4*)&g_QKV[base + d0] = qh;
    }

    size_t ap = ((size_t)(b * GROUPS + g)) * D_ + d0;
    *(float4*)&g_Apart[ap] = make_float4(accA0, accA1, accA2, accA3);
}

// ---------------- reduce A partials ----------------
__global__ void k_reduceA()
{
    int idx = blockIdx.x * blockDim.x + threadIdx.x;
    int b  = idx >> 10;
    int dd = idx & 1023;
    const float* p = g_Apart + (size_t)b * GROUPS * D_ + dd;
    float s = 0.f;
    #pragma unroll 8
    for (int g = 0; g < GROUPS; g++) s += p[(size_t)g * D_];
    g_A[idx] = s;
}

// ---------------- Y = A (*) Qhat -> bf16 ----------------
__global__ void __launch_bounds__(256) k_scaleY()
{
    size_t row = blockIdx.x;
    int t  = threadIdx.x;
    int d0 = 4 * t;
    int b  = (int)(row >> 13);
    float4 q = *(float4*)&g_QKV[row * E3 + d0];
    float4 a = *(const float4*)&g_A[b * D_ + d0];
    __nv_bfloat16* op = g_Y + row * D_ + d0;
    *(__nv_bfloat162*)(op)     = __floats2bfloat162_rn(q.x * a.x, q.y * a.y);
    *(__nv_bfloat162*)(op + 2) = __floats2bfloat162_rn(q.z * a.z, q.w * a.w);
}

// ---------------- launch ----------------
extern "C" void kernel_launch(void* const* d_in, const int* in_sizes, int n_in,
                              void* d_out, int out_size)
{
    const float* X    = (const float*)d_in[0];
    const float* Win  = (const float*)d_in[1];
    const float* Wout = (const float*)d_in[2];
    const float* lg   = (const float*)d_in[3];
    const float* lb   = (const float*)d_in[4];
    float* out = (float*)d_out;

    cudaFuncSetAttribute(k_gemm, cudaFuncAttributeMaxDynamicSharedMemorySize, GEMM_SMEM);

    k_convert<<<(E3 * D_) / 4 / 256, 256>>>(Win, 0, E3 * D_);
    k_convert<<<(D_ * D_) / 4 / 256, 256>>>(Wout, 1, D_ * D_);
    k_layernorm<<<NROWS, 256>>>(X, lg, lb);
    k_gemm<<<dim3(E3 / 128, NROWS / 128), 256, GEMM_SMEM>>>(nullptr, out, 0, E3);
    k_rowproc<<<B_ * GROUPS, 256>>>();
    k_reduceA<<<16, 256>>>();
    k_scaleY<<<NROWS, 256>>>();
    k_gemm<<<dim3(D_ / 128, NROWS / 128), 256, GEMM_SMEM>>>(X, out, 1, D_);
}

// round 5
// speedup vs baseline: 1.4014x; 1.3882x over previous
#include <cuda_runtime.h>
#include <cuda_bf16.h>
#include <math.h>
#include <stdint.h>

#define D_      1024
#define S_      8192
#define B_      4
#define NROWS   (B_ * S_)      // 32768
#define E3      (3 * D_)       // 3072
#define GROUPS  256
#define GSIZE   32

// ---------------- scratch (static __device__: allocation-free) ----------------
__device__ __nv_bfloat16 g_Xn  [(size_t)NROWS * D_];   // 64 MiB
__device__ __nv_bfloat16 g_Win [(size_t)E3 * D_];      // 6 MiB
__device__ __nv_bfloat16 g_Wpr [(size_t)B_ * D_ * D_]; // 8 MiB  (A-scaled W_out, per batch)
__device__ float         g_QKV [(size_t)NROWS * E3];   // 384 MiB
__device__ float         g_Apart[B_ * GROUPS * D_];
__device__ float         g_A   [B_ * D_];
__device__ __nv_bfloat16 g_Y   [(size_t)NROWS * D_];   // 64 MiB (Qhat, bf16)

__device__ __forceinline__ uint32_t smem_u32(const void* p) {
    uint32_t a;
    asm("{ .reg .u64 t; cvta.to.shared.u64 t, %1; cvt.u32.u64 %0, t; }" : "=r"(a) : "l"(p));
    return a;
}

// ---------------- fp32 -> bf16 weight conversion (W_in) ----------------
__global__ void k_convert(const float* __restrict__ src, int n)
{
    int i = (blockIdx.x * blockDim.x + threadIdx.x) * 4;
    if (i >= n) return;
    float4 v = *(const float4*)(src + i);
    *(__nv_bfloat162*)(g_Win + i)     = __floats2bfloat162_rn(v.x, v.y);
    *(__nv_bfloat162*)(g_Win + i + 2) = __floats2bfloat162_rn(v.z, v.w);
}

// ---------------- LayerNorm (one block per row) ----------------
__global__ void __launch_bounds__(256) k_layernorm(
    const float* __restrict__ X, const float* __restrict__ lg, const float* __restrict__ lb)
{
    int row = blockIdx.x;
    int t   = threadIdx.x;
    const float* xp = X + (size_t)row * D_ + 4 * t;
    float4 x = *(const float4*)xp;

    float s  = x.x + x.y + x.z + x.w;
    float sq = x.x * x.x + x.y * x.y + x.z * x.z + x.w * x.w;

    __shared__ float2 red[9];
    float2 v = make_float2(s, sq);
    #pragma unroll
    for (int o = 16; o; o >>= 1) {
        v.x += __shfl_xor_sync(0xffffffffu, v.x, o);
        v.y += __shfl_xor_sync(0xffffffffu, v.y, o);
    }
    if ((t & 31) == 0) red[t >> 5] = v;
    __syncthreads();
    if (t < 32) {
        float2 w = (t < 8) ? red[t] : make_float2(0.f, 0.f);
        #pragma unroll
        for (int o = 4; o; o >>= 1) {
            w.x += __shfl_xor_sync(0xffffffffu, w.x, o);
            w.y += __shfl_xor_sync(0xffffffffu, w.y, o);
        }
        if (t == 0) red[8] = w;
    }
    __syncthreads();
    float2 tot = red[8];

    float mu  = tot.x * (1.f / D_);
    float var = tot.y * (1.f / D_) - mu * mu;
    float rs  = rsqrtf(var + 1e-5f);

    float4 g4 = *(const float4*)(lg + 4 * t);
    float4 b4 = *(const float4*)(lb + 4 * t);
    float y0 = (x.x - mu) * rs * g4.x + b4.x;
    float y1 = (x.y - mu) * rs * g4.y + b4.y;
    float y2 = (x.z - mu) * rs * g4.z + b4.z;
    float y3 = (x.w - mu) * rs * g4.w + b4.w;

    __nv_bfloat16* op = g_Xn + (size_t)row * D_ + 4 * t;
    *(__nv_bfloat162*)(op)     = __floats2bfloat162_rn(y0, y1);
    *(__nv_bfloat162*)(op + 2) = __floats2bfloat162_rn(y2, y3);
}

// ---------------- mma.sync bf16 GEMM: C[m,n] = sum_k A[m,k]*W[n,k] (+X) ----------------
// 128x256 block tile, 8 warps (2m x 4n), warp tile 64x64, KC=64, 4-stage cp.async.
#define KC 64
#define NCHUNK 16
#define ASTAGE 16384
#define BSTAGE 32768
#define STAGE_BYTES (ASTAGE + BSTAGE)     // 48 KB
#define GEMM_SMEM (4 * STAGE_BYTES)       // 192 KB

__global__ void __launch_bounds__(256, 1) k_gemm(
    const float* __restrict__ addX, float* __restrict__ Cout, int mode, int N)
{
    extern __shared__ char smem[];
    const int K = 1024;
    const int tid  = threadIdx.x;
    const int w    = tid >> 5;
    const int lane = tid & 31;
    const int wm   = w & 1;          // 0..1 -> 64-row slice
    const int wn   = w >> 1;         // 0..3 -> 64-col slice
    const int m0 = blockIdx.y * 128;
    const int n0 = blockIdx.x * 256;

    const __nv_bfloat16* Ag = mode ? g_Y : g_Xn;
    const __nv_bfloat16* Bg = mode ? (g_Wpr + (size_t)(m0 >> 13) * D_ * D_) : g_Win;
    float* C = mode ? Cout : g_QKV;

    const uint32_t sbase = smem_u32(smem);

    auto issue = [&](int kt) {
        const uint32_t st = sbase + (kt & 3) * STAGE_BYTES;
        #pragma unroll
        for (int i = 0; i < 12; i++) {
            int vec = i * 256 + tid;          // 0..3071 ; A: 0-1023, B: 1024-3071
            int isB = vec >= 1024;
            int vv  = isB ? vec - 1024 : vec;
            int row = vv >> 3;
            int c   = vv & 7;
            const __nv_bfloat16* src =
                (isB ? Bg + (size_t)(n0 + row) * K : Ag + (size_t)(m0 + row) * K)
                + kt * KC + c * 8;
            uint32_t dst = st + (isB ? ASTAGE : 0) + row * 128 + (((c ^ (row & 7)) << 4));
            asm volatile("cp.async.cg.shared.global [%0], [%1], 16;" :: "r"(dst), "l"(src));
        }
        asm volatile("cp.async.commit_group;" ::: "memory");
    };

    float acc[4][8][4];
    #pragma unroll
    for (int mi = 0; mi < 4; mi++)
        #pragma unroll
        for (int ni = 0; ni < 8; ni++)
            #pragma unroll
            for (int e = 0; e < 4; e++) acc[mi][ni][e] = 0.f;

    issue(0); issue(1); issue(2);

    const int lr = lane & 15;
    const int lc = lane >> 4;

    uint32_t a[2][4][4], b[2][8][2];

    for (int kt = 0; kt < NCHUNK; kt++) {
        asm volatile("cp.async.wait_group 2;" ::: "memory");
        __syncthreads();
        if (kt + 3 < NCHUNK) issue(kt + 3);
        else asm volatile("cp.async.commit_group;" ::: "memory");

        const uint32_t sA = sbase + (kt & 3) * STAGE_BYTES;
        const uint32_t sB = sA + ASTAGE;

        // load fragments for ks=0 into buffer 0
        {
            const int c = lc;
            #pragma unroll
            for (int mi = 0; mi < 4; mi++) {
                int r = wm * 64 + mi * 16 + lr;
                uint32_t addr = sA + r * 128 + ((c ^ (r & 7)) << 4);
                asm volatile("ldmatrix.sync.aligned.m8n8.x4.shared.b16 {%0,%1,%2,%3}, [%4];"
                    : "=r"(a[0][mi][0]), "=r"(a[0][mi][1]), "=r"(a[0][mi][2]), "=r"(a[0][mi][3])
                    : "r"(addr));
            }
            #pragma unroll
            for (int nb = 0; nb < 4; nb++) {
                int r = wn * 64 + nb * 16 + lr;
                uint32_t addr = sB + r * 128 + ((c ^ (r & 7)) << 4);
                uint32_t t0, t1, t2, t3;
                asm volatile("ldmatrix.sync.aligned.m8n8.x4.shared.b16 {%0,%1,%2,%3}, [%4];"
                    : "=r"(t0), "=r"(t1), "=r"(t2), "=r"(t3) : "r"(addr));
                b[0][nb * 2][0] = t0; b[0][nb * 2][1] = t2;
                b[0][nb * 2 + 1][0] = t1; b[0][nb * 2 + 1][1] = t3;
            }
        }

        #pragma unroll
        for (int ks = 0; ks < 4; ks++) {
            const int cur = ks & 1;
            const int nxt = cur ^ 1;
            if (ks < 3) {
                const int c = (ks + 1) * 2 + lc;
                #pragma unroll
                for (int mi = 0; mi < 4; mi++) {
                    int r = wm * 64 + mi * 16 + lr;
                    uint32_t addr = sA + r * 128 + ((c ^ (r & 7)) << 4);
                    asm volatile("ldmatrix.sync.aligned.m8n8.x4.shared.b16 {%0,%1,%2,%3}, [%4];"
                        : "=r"(a[nxt][mi][0]), "=r"(a[nxt][mi][1]),
                          "=r"(a[nxt][mi][2]), "=r"(a[nxt][mi][3]) : "r"(addr));
                }
                #pragma unroll
                for (int nb = 0; nb < 4; nb++) {
                    int r = wn * 64 + nb * 16 + lr;
                    uint32_t addr = sB + r * 128 + ((c ^ (r & 7)) << 4);
                    uint32_t t0, t1, t2, t3;
                    asm volatile("ldmatrix.sync.aligned.m8n8.x4.shared.b16 {%0,%1,%2,%3}, [%4];"
                        : "=r"(t0), "=r"(t1), "=r"(t2), "=r"(t3) : "r"(addr));
                    b[nxt][nb * 2][0] = t0; b[nxt][nb * 2][1] = t2;
                    b[nxt][nb * 2 + 1][0] = t1; b[nxt][nb * 2 + 1][1] = t3;
                }
            }
            #pragma unroll
            for (int mi = 0; mi < 4; mi++)
                #pragma unroll
                for (int ni = 0; ni < 8; ni++) {
                    asm volatile(
                        "mma.sync.aligned.m16n8k16.row.col.f32.bf16.bf16.f32 "
                        "{%0,%1,%2,%3}, {%4,%5,%6,%7}, {%8,%9}, {%0,%1,%2,%3};"
                        : "+f"(acc[mi][ni][0]), "+f"(acc[mi][ni][1]),
                          "+f"(acc[mi][ni][2]), "+f"(acc[mi][ni][3])
                        : "r"(a[cur][mi][0]), "r"(a[cur][mi][1]),
                          "r"(a[cur][mi][2]), "r"(a[cur][mi][3]),
                          "r"(b[cur][ni][0]), "r"(b[cur][ni][1]));
                }
        }
    }

    // Epilogue: direct register -> gmem (float2), +X residual for mode 1.
    const int rbase = m0 + wm * 64 + (lane >> 2);
    const int cbase = n0 + wn * 64 + (lane & 3) * 2;
    #pragma unroll
    for (int mi = 0; mi < 4; mi++)
        #pragma unroll
        for (int ni = 0; ni < 8; ni++) {
            int rr = rbase + mi * 16;
            int cc = cbase + ni * 8;
            size_t i0 = (size_t)rr * N + cc;
            size_t i1 = (size_t)(rr + 8) * N + cc;
            float2 v0 = make_float2(acc[mi][ni][0], acc[mi][ni][1]);
            float2 v1 = make_float2(acc[mi][ni][2], acc[mi][ni][3]);
            if (addX) {
                float2 x0 = *(const float2*)(addX + i0);
                float2 x1 = *(const float2*)(addX + i1);
                v0.x += x0.x; v0.y += x0.y;
                v1.x += x1.x; v1.y += x1.y;
            }
            *(float2*)(C + i0) = v0;
            *(float2*)(C + i1) = v1;
        }
}

// ---------------- rotary + l2norms + A partial reduction ----------------
// Writes Qhat directly as bf16 into g_Y; accumulates per-group A partials.
__global__ void __launch_bounds__(256) k_rowproc()
{
    int bg = blockIdx.x;
    int b  = bg >> 8;
    int g  = bg & 255;
    int t  = threadIdx.x;
    int d0 = 4 * t;

    float invf0 = 0.f, invf1 = 0.f;
    bool rot = (d0 < 512);
    if (rot) {
        int i0 = 2 * t;
        invf0 = (float)(1.0 / pow(10000.0, (double)i0 * (1.0 / 256.0)));
        invf1 = (float)(1.0 / pow(10000.0, (double)(i0 + 1) * (1.0 / 256.0)));
    }

    float accA0 = 0.f, accA1 = 0.f, accA2 = 0.f, accA3 = 0.f;
    __shared__ float2 red[2][9];

    for (int r = 0; r < GSIZE; r++) {
        int s = g * GSIZE + r;
        size_t base = ((size_t)b * S_ + s) * E3;
        float4 q = *(float4*)&g_QKV[base + d0];
        float4 k = *(float4*)&g_QKV[base + 1024 + d0];
        float4 v = *(float4*)&g_QKV[base + 2048 + d0];

        if (rot) {
            float sn0, cs0, sn1, cs1;
            sincosf((float)s * invf0, &sn0, &cs0);
            sincosf((float)s * invf1, &sn1, &cs1);
            float a, bb;
            a = q.x * cs0 - q.y * sn0; bb = q.y * cs0 + q.x * sn0; q.x = a; q.y = bb;
            a = q.z * cs1 - q.w * sn1; bb = q.w * cs1 + q.z * sn1; q.z = a; q.w = bb;
            a = k.x * cs0 - k.y * sn0; bb = k.y * cs0 + k.x * sn0; k.x = a; k.y = bb;
            a = k.z * cs1 - k.w * sn1; bb = k.w * cs1 + k.z * sn1; k.z = a; k.w = bb;
        }

        float sk = k.x * k.x + k.y * k.y + k.z * k.z + k.w * k.w;
        float sq = q.x * q.x + q.y * q.y + q.z * q.z + q.w * q.w;
        float2 val = make_float2(sk, sq);
        #pragma unroll
        for (int o = 16; o; o >>= 1) {
            val.x += __shfl_xor_sync(0xffffffffu, val.x, o);
            val.y += __shfl_xor_sync(0xffffffffu, val.y, o);
        }
        int par = r & 1;
        if ((t & 31) == 0) red[par][t >> 5] = val;
        __syncthreads();
        if (t < 32) {
            float2 w2 = (t < 8) ? red[par][t] : make_float2(0.f, 0.f);
            #pragma unroll
            for (int o = 4; o; o >>= 1) {
                w2.x += __shfl_xor_sync(0xffffffffu, w2.x, o);
                w2.y += __shfl_xor_sync(0xffffffffu, w2.y, o);
            }
            if (t == 0) red[par][8] = w2;
        }
        __syncthreads();
        float2 tot = red[par][8];
        float kinv = rsqrtf(tot.x + 1e-6f);
        float qinv = rsqrtf(tot.y + 1e-6f);

        accA0 += k.x * kinv * v.x;
        accA1 += k.y * kinv * v.y;
        accA2 += k.z * kinv * v.z;
        accA3 += k.w * kinv * v.w;

        __nv_bfloat16* yp = g_Y + ((size_t)b * S_ + s) * D_ + d0;
        *(__nv_bfloat162*)(yp)     = __floats2bfloat162_rn(q.x * qinv, q.y * qinv);
        *(__nv_bfloat162*)(yp + 2) = __floats2bfloat162_rn(q.z * qinv, q.w * qinv);
    }

    size_t ap = ((size_t)(b * GROUPS + g)) * D_ + d0;
    *(float4*)&g_Apart[ap] = make_float4(accA0, accA1, accA2, accA3);
}

// ---------------- reduce A partials ----------------
__global__ void k_reduceA()
{
    int idx = blockIdx.x * blockDim.x + threadIdx.x;
    int b  = idx >> 10;
    int dd = idx & 1023;
    const float* p = g_Apart + (size_t)b * GROUPS * D_ + dd;
    float s = 0.f;
    #pragma unroll 8
    for (int g = 0; g < GROUPS; g++) s += p[(size_t)g * D_];
    g_A[idx] = s;
}

// ---------------- W'_b = A_b (*) W_out  -> bf16, 4 copies ----------------
__global__ void __launch_bounds__(256) k_scaleW(const float* __restrict__ Wout)
{
    int i4 = (blockIdx.x * blockDim.x + threadIdx.x) * 4;   // over D_*D_
    if (i4 >= D_ * D_) return;
    int d = i4 & 1023;
    float4 w = *(const float4*)(Wout + i4);
    #pragma unroll
    for (int b = 0; b < B_; b++) {
        float4 a = *(const float4*)(g_A + b * D_ + d);
        __nv_bfloat16* dst = g_Wpr + (size_t)b * D_ * D_ + i4;
        *(__nv_bfloat162*)(dst)     = __floats2bfloat162_rn(w.x * a.x, w.y * a.y);
        *(__nv_bfloat162*)(dst + 2) = __floats2bfloat162_rn(w.z * a.z, w.w * a.w);
    }
}

// ---------------- launch ----------------
extern "C" void kernel_launch(void* const* d_in, const int* in_sizes, int n_in,
                              void* d_out, int out_size)
{
    const float* X    = (const float*)d_in[0];
    const float* Win  = (const float*)d_in[1];
    const float* Wout = (const float*)d_in[2];
    const float* lg   = (const float*)d_in[3];
    const float* lb   = (const float*)d_in[4];
    float* out = (float*)d_out;

    cudaFuncSetAttribute(k_gemm, cudaFuncAttributeMaxDynamicSharedMemorySize, GEMM_SMEM);

    k_convert<<<(E3 * D_) / 4 / 256, 256>>>(Win, E3 * D_);
    k_layernorm<<<NROWS, 256>>>(X, lg, lb);
    k_gemm<<<dim3(E3 / 256, NROWS / 128), 256, GEMM_SMEM>>>(nullptr, out, 0, E3);
    k_rowproc<<<B_ * GROUPS, 256>>>();
    k_reduceA<<<16, 256>>>();
    k_scaleW<<<D_ * D_ / 4 / 256, 256>>>(Wout);
    k_gemm<<<dim3(D_ / 256, NROWS / 128), 256, GEMM_SMEM>>>(X, out, 1, D_);
}

// round 6
// speedup vs baseline: 1.4163x; 1.0107x over previous
#include <cuda_runtime.h>
#include <cuda_bf16.h>
#include <math.h>
#include <stdint.h>

#define D_      1024
#define S_      8192
#define B_      4
#define NROWS   (B_ * S_)      // 32768
#define E3      (3 * D_)       // 3072

// ---------------- scratch (static __device__: allocation-free) ----------------
__device__ __nv_bfloat16 g_Xn  [(size_t)NROWS * D_];   // 64 MiB
__device__ __nv_bfloat16 g_Win [(size_t)E3 * D_];      // 6 MiB
__device__ __nv_bfloat16 g_Wpr [(size_t)B_ * D_ * D_]; // 8 MiB  (A-scaled W_out, per batch)
__device__ __nv_bfloat16 g_Qb  [(size_t)NROWS * D_];   // 64 MiB
__device__ __nv_bfloat16 g_Kb  [(size_t)NROWS * D_];   // 64 MiB
__device__ float         g_V   [(size_t)NROWS * D_];   // 128 MiB
__device__ float         g_Apart[(size_t)4096 * D_];   // 16 MiB (per-warp partials)
__device__ float         g_A4  [4 * B_ * D_];
__device__ __nv_bfloat16 g_Y   [(size_t)NROWS * D_];   // 64 MiB (Qhat, bf16)

__device__ __forceinline__ uint32_t smem_u32(const void* p) {
    uint32_t a;
    asm("{ .reg .u64 t; cvta.to.shared.u64 t, %1; cvt.u32.u64 %0, t; }" : "=r"(a) : "l"(p));
    return a;
}

// ---------------- fp32 -> bf16 weight conversion (W_in) ----------------
__global__ void k_convert(const float* __restrict__ src, int n)
{
    int i = (blockIdx.x * blockDim.x + threadIdx.x) * 4;
    if (i >= n) return;
    float4 v = *(const float4*)(src + i);
    *(__nv_bfloat162*)(g_Win + i)     = __floats2bfloat162_rn(v.x, v.y);
    *(__nv_bfloat162*)(g_Win + i + 2) = __floats2bfloat162_rn(v.z, v.w);
}

// ---------------- LayerNorm (one block per row) ----------------
__global__ void __launch_bounds__(256) k_layernorm(
    const float* __restrict__ X, const float* __restrict__ lg, const float* __restrict__ lb)
{
    int row = blockIdx.x;
    int t   = threadIdx.x;
    const float* xp = X + (size_t)row * D_ + 4 * t;
    float4 x = *(const float4*)xp;

    float s  = x.x + x.y + x.z + x.w;
    float sq = x.x * x.x + x.y * x.y + x.z * x.z + x.w * x.w;

    __shared__ float2 red[9];
    float2 v = make_float2(s, sq);
    #pragma unroll
    for (int o = 16; o; o >>= 1) {
        v.x += __shfl_xor_sync(0xffffffffu, v.x, o);
        v.y += __shfl_xor_sync(0xffffffffu, v.y, o);
    }
    if ((t & 31) == 0) red[t >> 5] = v;
    __syncthreads();
    if (t < 32) {
        float2 w = (t < 8) ? red[t] : make_float2(0.f, 0.f);
        #pragma unroll
        for (int o = 4; o; o >>= 1) {
            w.x += __shfl_xor_sync(0xffffffffu, w.x, o);
            w.y += __shfl_xor_sync(0xffffffffu, w.y, o);
        }
        if (t == 0) red[8] = w;
    }
    __syncthreads();
    float2 tot = red[8];

    float mu  = tot.x * (1.f / D_);
    float var = tot.y * (1.f / D_) - mu * mu;
    float rs  = rsqrtf(var + 1e-5f);

    float4 g4 = *(const float4*)(lg + 4 * t);
    float4 b4 = *(const float4*)(lb + 4 * t);
    float y0 = (x.x - mu) * rs * g4.x + b4.x;
    float y1 = (x.y - mu) * rs * g4.y + b4.y;
    float y2 = (x.z - mu) * rs * g4.z + b4.z;
    float y3 = (x.w - mu) * rs * g4.w + b4.w;

    __nv_bfloat16* op = g_Xn + (size_t)row * D_ + 4 * t;
    *(__nv_bfloat162*)(op)     = __floats2bfloat162_rn(y0, y1);
    *(__nv_bfloat162*)(op + 2) = __floats2bfloat162_rn(y2, y3);
}

// ---------------- mma.sync bf16 GEMM ----------------
// 128x256 block tile, 8 warps (2m x 4n), warp tile 64x64, KC=64, 4-stage cp.async.
// mode 0: A=g_Xn, B=g_Win  (N=3072), C -> g_Qb/g_Kb (bf16) or g_V (fp32) by n-region
// mode 1: A=g_Y,  B=g_Wpr[batch], C -> out (fp32, += X)
#define KC 64
#define NCHUNK 16
#define ASTAGE 16384
#define BSTAGE 32768
#define STAGE_BYTES (ASTAGE + BSTAGE)     // 48 KB
#define GEMM_SMEM (4 * STAGE_BYTES)       // 192 KB

__global__ void __launch_bounds__(256, 1) k_gemm(
    const float* __restrict__ addX, float* __restrict__ Cout, int mode)
{
    extern __shared__ char smem[];
    const int K = 1024;
    const int tid  = threadIdx.x;
    const int w    = tid >> 5;
    const int lane = tid & 31;
    const int wm   = w & 1;          // 0..1 -> 64-row slice
    const int wn   = w >> 1;         // 0..3 -> 64-col slice
    const int m0 = blockIdx.y * 128;
    const int n0 = blockIdx.x * 256;

    const __nv_bfloat16* Ag = mode ? g_Y : g_Xn;
    const __nv_bfloat16* Bg = mode ? (g_Wpr + (size_t)(m0 >> 13) * D_ * D_) : g_Win;

    const uint32_t sbase = smem_u32(smem);

    auto issue = [&](int kt) {
        const uint32_t st = sbase + (kt & 3) * STAGE_BYTES;
        #pragma unroll
        for (int i = 0; i < 12; i++) {
            int vec = i * 256 + tid;          // 0..3071 ; A: 0-1023, B: 1024-3071
            int isB = vec >= 1024;
            int vv  = isB ? vec - 1024 : vec;
            int row = vv >> 3;
            int c   = vv & 7;
            const __nv_bfloat16* src =
                (isB ? Bg + (size_t)(n0 + row) * K : Ag + (size_t)(m0 + row) * K)
                + kt * KC + c * 8;
            uint32_t dst = st + (isB ? ASTAGE : 0) + row * 128 + (((c ^ (row & 7)) << 4));
            asm volatile("cp.async.cg.shared.global [%0], [%1], 16;" :: "r"(dst), "l"(src));
        }
        asm volatile("cp.async.commit_group;" ::: "memory");
    };

    float acc[4][8][4];
    #pragma unroll
    for (int mi = 0; mi < 4; mi++)
        #pragma unroll
        for (int ni = 0; ni < 8; ni++)
            #pragma unroll
            for (int e = 0; e < 4; e++) acc[mi][ni][e] = 0.f;

    issue(0); issue(1); issue(2);

    const int lr = lane & 15;
    const int lc = lane >> 4;

    uint32_t a[2][4][4], b[2][8][2];

    for (int kt = 0; kt < NCHUNK; kt++) {
        asm volatile("cp.async.wait_group 2;" ::: "memory");
        __syncthreads();
        if (kt + 3 < NCHUNK) issue(kt + 3);
        else asm volatile("cp.async.commit_group;" ::: "memory");

        const uint32_t sA = sbase + (kt & 3) * STAGE_BYTES;
        const uint32_t sB = sA + ASTAGE;

        {
            const int c = lc;
            #pragma unroll
            for (int mi = 0; mi < 4; mi++) {
                int r = wm * 64 + mi * 16 + lr;
                uint32_t addr = sA + r * 128 + ((c ^ (r & 7)) << 4);
                asm volatile("ldmatrix.sync.aligned.m8n8.x4.shared.b16 {%0,%1,%2,%3}, [%4];"
                    : "=r"(a[0][mi][0]), "=r"(a[0][mi][1]), "=r"(a[0][mi][2]), "=r"(a[0][mi][3])
                    : "r"(addr));
            }
            #pragma unroll
            for (int nb = 0; nb < 4; nb++) {
                int r = wn * 64 + nb * 16 + lr;
                uint32_t addr = sB + r * 128 + ((c ^ (r & 7)) << 4);
                uint32_t t0, t1, t2, t3;
                asm volatile("ldmatrix.sync.aligned.m8n8.x4.shared.b16 {%0,%1,%2,%3}, [%4];"
                    : "=r"(t0), "=r"(t1), "=r"(t2), "=r"(t3) : "r"(addr));
                b[0][nb * 2][0] = t0; b[0][nb * 2][1] = t2;
                b[0][nb * 2 + 1][0] = t1; b[0][nb * 2 + 1][1] = t3;
            }
        }

        #pragma unroll
        for (int ks = 0; ks < 4; ks++) {
            const int cur = ks & 1;
            const int nxt = cur ^ 1;
            if (ks < 3) {
                const int c = (ks + 1) * 2 + lc;
                #pragma unroll
                for (int mi = 0; mi < 4; mi++) {
                    int r = wm * 64 + mi * 16 + lr;
                    uint32_t addr = sA + r * 128 + ((c ^ (r & 7)) << 4);
                    asm volatile("ldmatrix.sync.aligned.m8n8.x4.shared.b16 {%0,%1,%2,%3}, [%4];"
                        : "=r"(a[nxt][mi][0]), "=r"(a[nxt][mi][1]),
                          "=r"(a[nxt][mi][2]), "=r"(a[nxt][mi][3]) : "r"(addr));
                }
                #pragma unroll
                for (int nb = 0; nb < 4; nb++) {
                    int r = wn * 64 + nb * 16 + lr;
                    uint32_t addr = sB + r * 128 + ((c ^ (r & 7)) << 4);
                    uint32_t t0, t1, t2, t3;
                    asm volatile("ldmatrix.sync.aligned.m8n8.x4.shared.b16 {%0,%1,%2,%3}, [%4];"
                        : "=r"(t0), "=r"(t1), "=r"(t2), "=r"(t3) : "r"(addr));
                    b[nxt][nb * 2][0] = t0; b[nxt][nb * 2][1] = t2;
                    b[nxt][nb * 2 + 1][0] = t1; b[nxt][nb * 2 + 1][1] = t3;
                }
            }
            #pragma unroll
            for (int mi = 0; mi < 4; mi++)
                #pragma unroll
                for (int ni = 0; ni < 8; ni++) {
                    asm volatile(
                        "mma.sync.aligned.m16n8k16.row.col.f32.bf16.bf16.f32 "
                        "{%0,%1,%2,%3}, {%4,%5,%6,%7}, {%8,%9}, {%0,%1,%2,%3};"
                        : "+f"(acc[mi][ni][0]), "+f"(acc[mi][ni][1]),
                          "+f"(acc[mi][ni][2]), "+f"(acc[mi][ni][3])
                        : "r"(a[cur][mi][0]), "r"(a[cur][mi][1]),
                          "r"(a[cur][mi][2]), "r"(a[cur][mi][3]),
                          "r"(b[cur][ni][0]), "r"(b[cur][ni][1]));
                }
        }
    }

    // Epilogue
    const int rbase = m0 + wm * 64 + (lane >> 2);
    if (mode) {
        const int cbase = n0 + wn * 64 + (lane & 3) * 2;
        #pragma unroll
        for (int mi = 0; mi < 4; mi++)
            #pragma unroll
            for (int ni = 0; ni < 8; ni++) {
                int rr = rbase + mi * 16;
                int cc = cbase + ni * 8;
                size_t i0 = (size_t)rr * D_ + cc;
                size_t i1 = (size_t)(rr + 8) * D_ + cc;
                float2 x0 = *(const float2*)(addX + i0);
                float2 x1 = *(const float2*)(addX + i1);
                *(float2*)(Cout + i0) = make_float2(acc[mi][ni][0] + x0.x, acc[mi][ni][1] + x0.y);
                *(float2*)(Cout + i1) = make_float2(acc[mi][ni][2] + x1.x, acc[mi][ni][3] + x1.y);
            }
    } else {
        const int region = n0 >> 10;           // 0=Q, 1=K, 2=V
        const int cbase  = (n0 & 1023) + wn * 64 + (lane & 3) * 2;
        if (region < 2) {
            __nv_bfloat16* Cb = region ? g_Kb : g_Qb;
            #pragma unroll
            for (int mi = 0; mi < 4; mi++)
                #pragma unroll
                for (int ni = 0; ni < 8; ni++) {
                    int rr = rbase + mi * 16;
                    int cc = cbase + ni * 8;
                    *(__nv_bfloat162*)(Cb + (size_t)rr * D_ + cc) =
                        __floats2bfloat162_rn(acc[mi][ni][0], acc[mi][ni][1]);
                    *(__nv_bfloat162*)(Cb + (size_t)(rr + 8) * D_ + cc) =
                        __floats2bfloat162_rn(acc[mi][ni][2], acc[mi][ni][3]);
                }
        } else {
            #pragma unroll
            for (int mi = 0; mi < 4; mi++)
                #pragma unroll
                for (int ni = 0; ni < 8; ni++) {
                    int rr = rbase + mi * 16;
                    int cc = cbase + ni * 8;
                    *(float2*)(g_V + (size_t)rr * D_ + cc) =
                        make_float2(acc[mi][ni][0], acc[mi][ni][1]);
                    *(float2*)(g_V + (size_t)(rr + 8) * D_ + cc) =
                        make_float2(acc[mi][ni][2], acc[mi][ni][3]);
                }
        }
    }
}

// ---------------- rotary + l2norms + A partials : warp-per-row, no barriers ----------------
// Block = 128 threads (4 warps); each warp owns 8 consecutive rows. Grid = NROWS/32.
__global__ void __launch_bounds__(128) k_rowproc()
{
    const int w    = threadIdx.x >> 5;
    const int lane = threadIdx.x & 31;
    const int row0 = blockIdx.x * 32 + w * 8;

    // invf for pair indices p0=2*lane+64k, p1=2*lane+1+64k ; invf(p)=1e4^(-p/256)
    float invf0[4], invf1[4];
    {
        double b0 = pow(10000.0, -(double)(2 * lane) * (1.0 / 256.0));
        double b1 = pow(10000.0, -(double)(2 * lane + 1) * (1.0 / 256.0));
        double f = 1.0;
        #pragma unroll
        for (int k = 0; k < 4; k++) {
            invf0[k] = (float)(b0 * f);
            invf1[k] = (float)(b1 * f);
            f *= 0.1;
        }
    }

    float accA[8][4];
    #pragma unroll
    for (int k = 0; k < 8; k++)
        #pragma unroll
        for (int e = 0; e < 4; e++) accA[k][e] = 0.f;

    const int c0 = 4 * lane;

    for (int r8 = 0; r8 < 8; r8++) {
        const int row = row0 + r8;
        const float s = (float)(row & 8191);
        const size_t base = (size_t)row * D_ + c0;

        float q[8][4], kk[8][4];
        float sq = 0.f, sk = 0.f;
        #pragma unroll
        for (int k = 0; k < 8; k++) {
            const __nv_bfloat162* qp = (const __nv_bfloat162*)(g_Qb + base + 128 * k);
            const __nv_bfloat162* kp = (const __nv_bfloat162*)(g_Kb + base + 128 * k);
            float2 qa = __bfloat1622float2(qp[0]);
            float2 qb = __bfloat1622float2(qp[1]);
            float2 ka = __bfloat1622float2(kp[0]);
            float2 kb = __bfloat1622float2(kp[1]);
            q[k][0] = qa.x; q[k][1] = qa.y; q[k][2] = qb.x; q[k][3] = qb.y;
            kk[k][0] = ka.x; kk[k][1] = ka.y; kk[k][2] = kb.x; kk[k][3] = kb.y;
            if (k < 4) {
                float sn0, cs0, sn1, cs1;
                sincosf(s * invf0[k], &sn0, &cs0);
                sincosf(s * invf1[k], &sn1, &cs1);
                float a, bb;
                a = q[k][0] * cs0 - q[k][1] * sn0; bb = q[k][1] * cs0 + q[k][0] * sn0;
                q[k][0] = a; q[k][1] = bb;
                a = q[k][2] * cs1 - q[k][3] * sn1; bb = q[k][3] * cs1 + q[k][2] * sn1;
                q[k][2] = a; q[k][3] = bb;
                a = kk[k][0] * cs0 - kk[k][1] * sn0; bb = kk[k][1] * cs0 + kk[k][0] * sn0;
                kk[k][0] = a; kk[k][1] = bb;
                a = kk[k][2] * cs1 - kk[k][3] * sn1; bb = kk[k][3] * cs1 + kk[k][2] * sn1;
                kk[k][2] = a; kk[k][3] = bb;
            }
            #pragma unroll
            for (int e = 0; e < 4; e++) {
                sq += q[k][e] * q[k][e];
                sk += kk[k][e] * kk[k][e];
            }
        }
        #pragma unroll
        for (int o = 16; o; o >>= 1) {
            sq += __shfl_xor_sync(0xffffffffu, sq, o);
            sk += __shfl_xor_sync(0xffffffffu, sk, o);
        }
        const float qi = rsqrtf(sq + 1e-6f);
        const float ki = rsqrtf(sk + 1e-6f);

        #pragma unroll
        for (int k = 0; k < 8; k++) {
            float4 v = *(const float4*)(g_V + base + 128 * k);
            accA[k][0] += kk[k][0] * ki * v.x;
            accA[k][1] += kk[k][1] * ki * v.y;
            accA[k][2] += kk[k][2] * ki * v.z;
            accA[k][3] += kk[k][3] * ki * v.w;
            __nv_bfloat16* yp = g_Y + base + 128 * k;
            *(__nv_bfloat162*)(yp)     = __floats2bfloat162_rn(q[k][0] * qi, q[k][1] * qi);
            *(__nv_bfloat162*)(yp + 2) = __floats2bfloat162_rn(q[k][2] * qi, q[k][3] * qi);
        }
    }

    const size_t ap = ((size_t)(blockIdx.x * 4 + w)) * D_ + c0;
    #pragma unroll
    for (int k = 0; k < 8; k++)
        *(float4*)&g_Apart[ap + 128 * k] =
            make_float4(accA[k][0], accA[k][1], accA[k][2], accA[k][3]);
}

// ---------------- reduce A partials (stage 1: 4096 groups -> 4x per (b,d)) ----------------
__global__ void k_reduceA()
{
    int idx = blockIdx.x * blockDim.x + threadIdx.x;   // 0..16383
    int sub = idx >> 12;
    int rem = idx & 4095;
    int b   = rem >> 10;
    int d   = rem & 1023;
    int g0  = b * 1024 + sub * 256;
    const float* p = g_Apart + (size_t)g0 * D_ + d;
    float s = 0.f;
    #pragma unroll 8
    for (int g = 0; g < 256; g++) s += p[(size_t)g * D_];
    g_A4[sub * 4096 + rem] = s;
}

// ---------------- W'_b = A_b (*) W_out  -> bf16, 4 copies (folds stage-2 reduce) ------------
__global__ void __launch_bounds__(256) k_scaleW(const float* __restrict__ Wout)
{
    int i4 = (blockIdx.x * blockDim.x + threadIdx.x) * 4;   // over D_*D_
    if (i4 >= D_ * D_) return;
    int d = i4 & 1023;
    float4 w = *(const float4*)(Wout + i4);
    #pragma unroll
    for (int b = 0; b < B_; b++) {
        float4 a = make_float4(0.f, 0.f, 0.f, 0.f);
        #pragma unroll
        for (int sub = 0; sub < 4; sub++) {
            float4 t = *(const float4*)(g_A4 + sub * 4096 + b * 1024 + d);
            a.x += t.x; a.y += t.y; a.z += t.z; a.w += t.w;
        }
        __nv_bfloat16* dst = g_Wpr + (size_t)b * D_ * D_ + i4;
        *(__nv_bfloat162*)(dst)     = __floats2bfloat162_rn(w.x * a.x, w.y * a.y);
        *(__nv_bfloat162*)(dst + 2) = __floats2bfloat162_rn(w.z * a.z, w.w * a.w);
    }
}

// ---------------- launch ----------------
extern "C" void kernel_launch(void* const* d_in, const int* in_sizes, int n_in,
                              void* d_out, int out_size)
{
    const float* X    = (const float*)d_in[0];
    const float* Win  = (const float*)d_in[1];
    const float* Wout = (const float*)d_in[2];
    const float* lg   = (const float*)d_in[3];
    const float* lb   = (const float*)d_in[4];
    float* out = (float*)d_out;

    cudaFuncSetAttribute(k_gemm, cudaFuncAttributeMaxDynamicSharedMemorySize, GEMM_SMEM);

    k_convert<<<(E3 * D_) / 4 / 256, 256>>>(Win, E3 * D_);
    k_layernorm<<<NROWS, 256>>>(X, lg, lb);
    k_gemm<<<dim3(E3 / 256, NROWS / 128), 256, GEMM_SMEM>>>(nullptr, nullptr, 0);
    k_rowproc<<<NROWS / 32, 128>>>();
    k_reduceA<<<64, 256>>>();
    k_scaleW<<<D_ * D_ / 4 / 256, 256>>>(Wout);
    k_gemm<<<dim3(D_ / 256, NROWS / 128), 256, GEMM_SMEM>>>(X, out, 1);
}

// round 7
// speedup vs baseline: 1.4417x; 1.0179x over previous
#include <cuda_runtime.h>
#include <cuda_bf16.h>
#include <math.h>
#include <stdint.h>

#define D_      1024
#define S_      8192
#define B_      4
#define NROWS   (B_ * S_)      // 32768
#define E3      (3 * D_)       // 3072

// ---------------- scratch (static __device__: allocation-free) ----------------
__device__ __nv_bfloat16 g_Xn  [(size_t)NROWS * D_];   // 64 MiB
__device__ __nv_bfloat16 g_Win [(size_t)E3 * D_];      // 6 MiB
__device__ __nv_bfloat16 g_Wpr [(size_t)B_ * D_ * D_]; // 8 MiB  (A-scaled W_out, per batch)
__device__ __nv_bfloat16 g_Qb  [(size_t)NROWS * D_];   // 64 MiB
__device__ __nv_bfloat16 g_Kb  [(size_t)NROWS * D_];   // 64 MiB
__device__ float         g_V   [(size_t)NROWS * D_];   // 128 MiB
__device__ float         g_Apart[(size_t)4096 * D_];   // 16 MiB (per-warp partials)
__device__ float         g_A8  [8 * B_ * D_];
__device__ __nv_bfloat16 g_Y   [(size_t)NROWS * D_];   // 64 MiB (Qhat, bf16)

__device__ __forceinline__ uint32_t smem_u32(const void* p) {
    uint32_t a;
    asm("{ .reg .u64 t; cvta.to.shared.u64 t, %1; cvt.u32.u64 %0, t; }" : "=r"(a) : "l"(p));
    return a;
}

// ---------------- fp32 -> bf16 weight conversion (W_in) ----------------
__global__ void k_convert(const float* __restrict__ src, int n)
{
    int i = (blockIdx.x * blockDim.x + threadIdx.x) * 4;
    if (i >= n) return;
    float4 v = *(const float4*)(src + i);
    *(__nv_bfloat162*)(g_Win + i)     = __floats2bfloat162_rn(v.x, v.y);
    *(__nv_bfloat162*)(g_Win + i + 2) = __floats2bfloat162_rn(v.z, v.w);
}

// ---------------- LayerNorm: warp-per-row, no barriers ----------------
// Block 256 (8 warps), each warp one row; grid = NROWS/8.
__global__ void __launch_bounds__(256) k_layernorm(
    const float* __restrict__ X, const float* __restrict__ lg, const float* __restrict__ lb)
{
    const int w    = threadIdx.x >> 5;
    const int lane = threadIdx.x & 31;
    const int row  = blockIdx.x * 8 + w;
    const int c0   = 4 * lane;
    const float* xp = X + (size_t)row * D_ + c0;

    float x[8][4];
    float s = 0.f, sq = 0.f;
    #pragma unroll
    for (int k = 0; k < 8; k++) {
        float4 v = *(const float4*)(xp + 128 * k);
        x[k][0] = v.x; x[k][1] = v.y; x[k][2] = v.z; x[k][3] = v.w;
        s  += v.x + v.y + v.z + v.w;
        sq += v.x * v.x + v.y * v.y + v.z * v.z + v.w * v.w;
    }
    #pragma unroll
    for (int o = 16; o; o >>= 1) {
        s  += __shfl_xor_sync(0xffffffffu, s, o);
        sq += __shfl_xor_sync(0xffffffffu, sq, o);
    }
    const float mu  = s * (1.f / D_);
    const float var = sq * (1.f / D_) - mu * mu;
    const float rs  = rsqrtf(var + 1e-5f);

    __nv_bfloat16* op = g_Xn + (size_t)row * D_ + c0;
    #pragma unroll
    for (int k = 0; k < 8; k++) {
        float4 g4 = *(const float4*)(lg + c0 + 128 * k);
        float4 b4 = *(const float4*)(lb + c0 + 128 * k);
        float y0 = (x[k][0] - mu) * rs * g4.x + b4.x;
        float y1 = (x[k][1] - mu) * rs * g4.y + b4.y;
        float y2 = (x[k][2] - mu) * rs * g4.z + b4.z;
        float y3 = (x[k][3] - mu) * rs * g4.w + b4.w;
        *(__nv_bfloat162*)(op + 128 * k)     = __floats2bfloat162_rn(y0, y1);
        *(__nv_bfloat162*)(op + 128 * k + 2) = __floats2bfloat162_rn(y2, y3);
    }
}

// ---------------- mma.sync bf16 GEMM ----------------
// 128x256 block tile, 8 warps (2m x 4n), warp tile 64x64, KC=64, 4-stage cp.async.
#define KC 64
#define NCHUNK 16
#define ASTAGE 16384
#define BSTAGE 32768
#define STAGE_BYTES (ASTAGE + BSTAGE)     // 48 KB
#define GEMM_SMEM (4 * STAGE_BYTES)       // 192 KB

__global__ void __launch_bounds__(256, 1) k_gemm(
    const float* __restrict__ addX, float* __restrict__ Cout, int mode)
{
    extern __shared__ char smem[];
    const int K = 1024;
    const int tid  = threadIdx.x;
    const int w    = tid >> 5;
    const int lane = tid & 31;
    const int wm   = w & 1;
    const int wn   = w >> 1;
    const int m0 = blockIdx.y * 128;
    const int n0 = blockIdx.x * 256;

    const __nv_bfloat16* Ag = mode ? g_Y : g_Xn;
    const __nv_bfloat16* Bg = mode ? (g_Wpr + (size_t)(m0 >> 13) * D_ * D_) : g_Win;

    const uint32_t sbase = smem_u32(smem);

    auto issue = [&](int kt) {
        const uint32_t st = sbase + (kt & 3) * STAGE_BYTES;
        #pragma unroll
        for (int i = 0; i < 12; i++) {
            int vec = i * 256 + tid;
            int isB = vec >= 1024;
            int vv  = isB ? vec - 1024 : vec;
            int row = vv >> 3;
            int c   = vv & 7;
            const __nv_bfloat16* src =
                (isB ? Bg + (size_t)(n0 + row) * K : Ag + (size_t)(m0 + row) * K)
                + kt * KC + c * 8;
            uint32_t dst = st + (isB ? ASTAGE : 0) + row * 128 + (((c ^ (row & 7)) << 4));
            asm volatile("cp.async.cg.shared.global [%0], [%1], 16;" :: "r"(dst), "l"(src));
        }
        asm volatile("cp.async.commit_group;" ::: "memory");
    };

    float acc[4][8][4];
    #pragma unroll
    for (int mi = 0; mi < 4; mi++)
        #pragma unroll
        for (int ni = 0; ni < 8; ni++)
            #pragma unroll
            for (int e = 0; e < 4; e++) acc[mi][ni][e] = 0.f;

    issue(0); issue(1); issue(2);

    const int lr = lane & 15;
    const int lc = lane >> 4;

    uint32_t a[2][4][4], b[2][8][2];

    for (int kt = 0; kt < NCHUNK; kt++) {
        asm volatile("cp.async.wait_group 2;" ::: "memory");
        __syncthreads();
        if (kt + 3 < NCHUNK) issue(kt + 3);
        else asm volatile("cp.async.commit_group;" ::: "memory");

        const uint32_t sA = sbase + (kt & 3) * STAGE_BYTES;
        const uint32_t sB = sA + ASTAGE;

        {
            const int c = lc;
            #pragma unroll
            for (int mi = 0; mi < 4; mi++) {
                int r = wm * 64 + mi * 16 + lr;
                uint32_t addr = sA + r * 128 + ((c ^ (r & 7)) << 4);
                asm volatile("ldmatrix.sync.aligned.m8n8.x4.shared.b16 {%0,%1,%2,%3}, [%4];"
                    : "=r"(a[0][mi][0]), "=r"(a[0][mi][1]), "=r"(a[0][mi][2]), "=r"(a[0][mi][3])
                    : "r"(addr));
            }
            #pragma unroll
            for (int nb = 0; nb < 4; nb++) {
                int r = wn * 64 + nb * 16 + lr;
                uint32_t addr = sB + r * 128 + ((c ^ (r & 7)) << 4);
                uint32_t t0, t1, t2, t3;
                asm volatile("ldmatrix.sync.aligned.m8n8.x4.shared.b16 {%0,%1,%2,%3}, [%4];"
                    : "=r"(t0), "=r"(t1), "=r"(t2), "=r"(t3) : "r"(addr));
                b[0][nb * 2][0] = t0; b[0][nb * 2][1] = t2;
                b[0][nb * 2 + 1][0] = t1; b[0][nb * 2 + 1][1] = t3;
            }
        }

        #pragma unroll
        for (int ks = 0; ks < 4; ks++) {
            const int cur = ks & 1;
            const int nxt = cur ^ 1;
            if (ks < 3) {
                const int c = (ks + 1) * 2 + lc;
                #pragma unroll
                for (int mi = 0; mi < 4; mi++) {
                    int r = wm * 64 + mi * 16 + lr;
                    uint32_t addr = sA + r * 128 + ((c ^ (r & 7)) << 4);
                    asm volatile("ldmatrix.sync.aligned.m8n8.x4.shared.b16 {%0,%1,%2,%3}, [%4];"
                        : "=r"(a[nxt][mi][0]), "=r"(a[nxt][mi][1]),
                          "=r"(a[nxt][mi][2]), "=r"(a[nxt][mi][3]) : "r"(addr));
                }
                #pragma unroll
                for (int nb = 0; nb < 4; nb++) {
                    int r = wn * 64 + nb * 16 + lr;
                    uint32_t addr = sB + r * 128 + ((c ^ (r & 7)) << 4);
                    uint32_t t0, t1, t2, t3;
                    asm volatile("ldmatrix.sync.aligned.m8n8.x4.shared.b16 {%0,%1,%2,%3}, [%4];"
                        : "=r"(t0), "=r"(t1), "=r"(t2), "=r"(t3) : "r"(addr));
                    b[nxt][nb * 2][0] = t0; b[nxt][nb * 2][1] = t2;
                    b[nxt][nb * 2 + 1][0] = t1; b[nxt][nb * 2 + 1][1] = t3;
                }
            }
            #pragma unroll
            for (int mi = 0; mi < 4; mi++)
                #pragma unroll
                for (int ni = 0; ni < 8; ni++) {
                    asm volatile(
                        "mma.sync.aligned.m16n8k16.row.col.f32.bf16.bf16.f32 "
                        "{%0,%1,%2,%3}, {%4,%5,%6,%7}, {%8,%9}, {%0,%1,%2,%3};"
                        : "+f"(acc[mi][ni][0]), "+f"(acc[mi][ni][1]),
                          "+f"(acc[mi][ni][2]), "+f"(acc[mi][ni][3])
                        : "r"(a[cur][mi][0]), "r"(a[cur][mi][1]),
                          "r"(a[cur][mi][2]), "r"(a[cur][mi][3]),
                          "r"(b[cur][ni][0]), "r"(b[cur][ni][1]));
                }
        }
    }

    const int rbase = m0 + wm * 64 + (lane >> 2);
    if (mode) {
        const int cbase = n0 + wn * 64 + (lane & 3) * 2;
        #pragma unroll
        for (int mi = 0; mi < 4; mi++)
            #pragma unroll
            for (int ni = 0; ni < 8; ni++) {
                int rr = rbase + mi * 16;
                int cc = cbase + ni * 8;
                size_t i0 = (size_t)rr * D_ + cc;
                size_t i1 = (size_t)(rr + 8) * D_ + cc;
                float2 x0 = *(const float2*)(addX + i0);
                float2 x1 = *(const float2*)(addX + i1);
                *(float2*)(Cout + i0) = make_float2(acc[mi][ni][0] + x0.x, acc[mi][ni][1] + x0.y);
                *(float2*)(Cout + i1) = make_float2(acc[mi][ni][2] + x1.x, acc[mi][ni][3] + x1.y);
            }
    } else {
        const int region = n0 >> 10;           // 0=Q, 1=K, 2=V
        const int cbase  = (n0 & 1023) + wn * 64 + (lane & 3) * 2;
        if (region < 2) {
            __nv_bfloat16* Cb = region ? g_Kb : g_Qb;
            #pragma unroll
            for (int mi = 0; mi < 4; mi++)
                #pragma unroll
                for (int ni = 0; ni < 8; ni++) {
                    int rr = rbase + mi * 16;
                    int cc = cbase + ni * 8;
                    *(__nv_bfloat162*)(Cb + (size_t)rr * D_ + cc) =
                        __floats2bfloat162_rn(acc[mi][ni][0], acc[mi][ni][1]);
                    *(__nv_bfloat162*)(Cb + (size_t)(rr + 8) * D_ + cc) =
                        __floats2bfloat162_rn(acc[mi][ni][2], acc[mi][ni][3]);
                }
        } else {
            #pragma unroll
            for (int mi = 0; mi < 4; mi++)
                #pragma unroll
                for (int ni = 0; ni < 8; ni++) {
                    int rr = rbase + mi * 16;
                    int cc = cbase + ni * 8;
                    *(float2*)(g_V + (size_t)rr * D_ + cc) =
                        make_float2(acc[mi][ni][0], acc[mi][ni][1]);
                    *(float2*)(g_V + (size_t)(rr + 8) * D_ + cc) =
                        make_float2(acc[mi][ni][2], acc[mi][ni][3]);
                }
        }
    }
}

// ---------------- rotary + l2norms + A partials : warp-per-row, two-pass ----------------
// Norm pass uses UNROTATED Q/K (rotation is orthogonal -> norm invariant), holding
// nothing in registers (asm loads prevent CSE); second pass reloads (L1-hot),
// applies rotary, writes Qhat, accumulates A. Block 256 (8 warps), warp owns 8 rows.
__global__ void __launch_bounds__(256) k_rowproc()
{
    const int w     = threadIdx.x >> 5;
    const int lane  = threadIdx.x & 31;
    const int gwarp = blockIdx.x * 8 + w;     // 0..4095
    const int row0  = gwarp * 8;

    float invf0[4], invf1[4];
    {
        double b0 = pow(10000.0, -(double)(2 * lane) * (1.0 / 256.0));
        double b1 = pow(10000.0, -(double)(2 * lane + 1) * (1.0 / 256.0));
        double f = 1.0;
        #pragma unroll
        for (int k = 0; k < 4; k++) {
            invf0[k] = (float)(b0 * f);
            invf1[k] = (float)(b1 * f);
            f *= 0.1;
        }
    }

    float accA[8][4];
    #pragma unroll
    for (int k = 0; k < 8; k++)
        #pragma unroll
        for (int e = 0; e < 4; e++) accA[k][e] = 0.f;

    const int c0 = 4 * lane;

    for (int r8 = 0; r8 < 8; r8++) {
        const int row = row0 + r8;
        const float s = (float)(row & 8191);
        const size_t base = (size_t)row * D_ + c0;
        const __nv_bfloat16* qrow = g_Qb + base;
        const __nv_bfloat16* krow = g_Kb + base;

        // ---- pass A: squares of unrotated Q/K (opaque loads, nothing held) ----
        float sq = 0.f, sk = 0.f;
        #pragma unroll
        for (int k = 0; k < 8; k++) {
            uint32_t q0, q1, k0, k1;
            asm volatile("ld.global.nc.v2.u32 {%0,%1}, [%2];"
                         : "=r"(q0), "=r"(q1) : "l"(qrow + 128 * k));
            asm volatile("ld.global.nc.v2.u32 {%0,%1}, [%2];"
                         : "=r"(k0), "=r"(k1) : "l"(krow + 128 * k));
            float2 qa = __bfloat1622float2(*(__nv_bfloat162*)&q0);
            float2 qb = __bfloat1622float2(*(__nv_bfloat162*)&q1);
            float2 ka = __bfloat1622float2(*(__nv_bfloat162*)&k0);
            float2 kb = __bfloat1622float2(*(__nv_bfloat162*)&k1);
            sq += qa.x * qa.x + qa.y * qa.y + qb.x * qb.x + qb.y * qb.y;
            sk += ka.x * ka.x + ka.y * ka.y + kb.x * kb.x + kb.y * kb.y;
        }
        #pragma unroll
        for (int o = 16; o; o >>= 1) {
            sq += __shfl_xor_sync(0xffffffffu, sq, o);
            sk += __shfl_xor_sync(0xffffffffu, sk, o);
        }
        const float qi = rsqrtf(sq + 1e-6f);
        const float ki = rsqrtf(sk + 1e-6f);

        // ---- pass B: reload, rotate, scale, store Qhat, accumulate A ----
        #pragma unroll
        for (int k = 0; k < 8; k++) {
            const __nv_bfloat162* qp = (const __nv_bfloat162*)(qrow + 128 * k);
            const __nv_bfloat162* kp = (const __nv_bfloat162*)(krow + 128 * k);
            float2 qa = __bfloat1622float2(qp[0]);
            float2 qb = __bfloat1622float2(qp[1]);
            float2 ka = __bfloat1622float2(kp[0]);
            float2 kb = __bfloat1622float2(kp[1]);
            if (k < 4) {
                float sn0, cs0, sn1, cs1;
                sincosf(s * invf0[k], &sn0, &cs0);
                sincosf(s * invf1[k], &sn1, &cs1);
                float a, bb;
                a = qa.x * cs0 - qa.y * sn0; bb = qa.y * cs0 + qa.x * sn0; qa.x = a; qa.y = bb;
                a = qb.x * cs1 - qb.y * sn1; bb = qb.y * cs1 + qb.x * sn1; qb.x = a; qb.y = bb;
                a = ka.x * cs0 - ka.y * sn0; bb = ka.y * cs0 + ka.x * sn0; ka.x = a; ka.y = bb;
                a = kb.x * cs1 - kb.y * sn1; bb = kb.y * cs1 + kb.x * sn1; kb.x = a; kb.y = bb;
            }
            float4 v = *(const float4*)(g_V + base + 128 * k);
            accA[k][0] += ka.x * ki * v.x;
            accA[k][1] += ka.y * ki * v.y;
            accA[k][2] += kb.x * ki * v.z;
            accA[k][3] += kb.y * ki * v.w;
            __nv_bfloat16* yp = g_Y + base + 128 * k;
            *(__nv_bfloat162*)(yp)     = __floats2bfloat162_rn(qa.x * qi, qa.y * qi);
            *(__nv_bfloat162*)(yp + 2) = __floats2bfloat162_rn(qb.x * qi, qb.y * qi);
        }
    }

    const size_t ap = (size_t)gwarp * D_ + c0;
    #pragma unroll
    for (int k = 0; k < 8; k++)
        *(float4*)&g_Apart[ap + 128 * k] =
            make_float4(accA[k][0], accA[k][1], accA[k][2], accA[k][3]);
}

// ---------------- reduce A partials (stage 1: 4096 groups -> 8x per (b,d)) ----------------
__global__ void k_reduceA()
{
    int idx = blockIdx.x * blockDim.x + threadIdx.x;   // 0..32767
    int sub = idx >> 12;       // 0..7
    int rem = idx & 4095;      // b*1024 + d
    int b   = rem >> 10;
    int d   = rem & 1023;
    int g0  = b * 1024 + sub * 128;
    const float* p = g_Apart + (size_t)g0 * D_ + d;
    float s = 0.f;
    #pragma unroll 8
    for (int g = 0; g < 128; g++) s += p[(size_t)g * D_];
    g_A8[sub * 4096 + rem] = s;
}

// ---------------- W'_b = A_b (*) W_out  -> bf16, 4 copies (folds stage-2 reduce) ------------
__global__ void __launch_bounds__(256) k_scaleW(const float* __restrict__ Wout)
{
    int i4 = (blockIdx.x * blockDim.x + threadIdx.x) * 4;   // over D_*D_
    if (i4 >= D_ * D_) return;
    int d = i4 & 1023;
    float4 w = *(const float4*)(Wout + i4);
    #pragma unroll
    for (int b = 0; b < B_; b++) {
        float4 a = make_float4(0.f, 0.f, 0.f, 0.f);
        #pragma unroll
        for (int sub = 0; sub < 8; sub++) {
            float4 t = *(const float4*)(g_A8 + sub * 4096 + b * 1024 + d);
            a.x += t.x; a.y += t.y; a.z += t.z; a.w += t.w;
        }
        __nv_bfloat16* dst = g_Wpr + (size_t)b * D_ * D_ + i4;
        *(__nv_bfloat162*)(dst)     = __floats2bfloat162_rn(w.x * a.x, w.y * a.y);
        *(__nv_bfloat162*)(dst + 2) = __floats2bfloat162_rn(w.z * a.z, w.w * a.w);
    }
}

// ---------------- launch ----------------
extern "C" void kernel_launch(void* const* d_in, const int* in_sizes, int n_in,
                              void* d_out, int out_size)
{
    const float* X    = (const float*)d_in[0];
    const float* Win  = (const float*)d_in[1];
    const float* Wout = (const float*)d_in[2];
    const float* lg   = (const float*)d_in[3];
    const float* lb   = (const float*)d_in[4];
    float* out = (float*)d_out;

    cudaFuncSetAttribute(k_gemm, cudaFuncAttributeMaxDynamicSharedMemorySize, GEMM_SMEM);

    k_convert<<<(E3 * D_) / 4 / 256, 256>>>(Win, E3 * D_);
    k_layernorm<<<NROWS / 8, 256>>>(X, lg, lb);
    k_gemm<<<dim3(E3 / 256, NROWS / 128), 256, GEMM_SMEM>>>(nullptr, nullptr, 0);
    k_rowproc<<<NROWS / 64, 256>>>();
    k_reduceA<<<128, 256>>>();
    k_scaleW<<<D_ * D_ / 4 / 256, 256>>>(Wout);
    k_gemm<<<dim3(D_ / 256, NROWS / 128), 256, GEMM_SMEM>>>(X, out, 1);
}